// round 5
// baseline (speedup 1.0000x reference)
#include <cuda_runtime.h>

#define H 28
#define W 28
#define NSQ (H * W)       // 784 pixels
#define OUTER NSQ         // outer face (+inf)
#define NN (NSQ + 1)
#define CARD 50

__global__ __launch_bounds__(1024, 1)
void cubical_kernel(const float* __restrict__ I, const float* __restrict__ p,
                    float* __restrict__ out) {
    __shared__ float Ip[NSQ];
    __shared__ short vord[NSQ];               // rank -> vertex
    __shared__ short pos[NSQ];                // vertex -> rank
    __shared__ unsigned long long nbrs[NSQ];  // per-rank packed nbr list
    __shared__ float sval[NSQ];               // per-rank vertex value
    __shared__ int2  node[NN];                // .x parent, .y cmax bits
    __shared__ float pw[NSQ], pd[NSQ];        // pairs (birth, death)
    __shared__ int   npairs;

    const int t = threadIdx.x;
    const float p0 = p[0], p1 = p[1];

    // ---- Phase 1: Ip = I . p, union-find init ----
    if (t < NSQ) {
        float v = fmaf(I[2 * t], p0, I[2 * t + 1] * p1);
        Ip[t] = v;
        node[t] = make_int2(t, __float_as_int(v));
    }
    if (t == 0) {
        node[OUTER] = make_int2(OUTER, __float_as_int(3.0e38f));
        npairs = 0;
    }
    __syncthreads();

    // ---- Phase 2: rank vertices descending (ties: index asc), unique ranks ----
    if (t < NSQ) {
        float wi = Ip[t];
        int rank = 0;
        #pragma unroll 4
        for (int j = 0; j < NSQ; j++) {
            float wj = Ip[j];
            rank += (wj > wi) || (wj == wi && j < t);
        }
        vord[rank] = (short)t;
        pos[t] = (short)rank;
    }
    __syncthreads();

    // ---- Phase 2.5: per-rank packed active-neighbor lists (parallel) ----
    // layout: bits[2:0]=cnt (0..4), bit[3]=outer, ids at bits[4+10i : 14+10i)
    if (t < NSQ) {
        const int k = t;
        const int v = vord[k];
        const int row = v / W, col = v - row * W;
        unsigned long long nb = 0;
        int cnt = 0;
        if (col > 0     && pos[v - 1] < k) { nb |= ((unsigned long long)(v - 1)) << (4 + 10 * cnt); cnt++; }
        if (col < W - 1 && pos[v + 1] < k) { nb |= ((unsigned long long)(v + 1)) << (4 + 10 * cnt); cnt++; }
        if (row > 0     && pos[v - W] < k) { nb |= ((unsigned long long)(v - W)) << (4 + 10 * cnt); cnt++; }
        if (row < H - 1 && pos[v + W] < k) { nb |= ((unsigned long long)(v + W)) << (4 + 10 * cnt); cnt++; }
        bool outer = (col == 0) | (col == W - 1) | (row == 0) | (row == H - 1);
        nb |= (unsigned long long)cnt | (outer ? 8ull : 0ull);
        nbrs[k] = nb;
        sval[k] = Ip[v];
    }
    __syncthreads();

    // ---- Phase 3: single-thread descending vertex sweep (elder rule) ----
    // superlevel H0 merges == reference's dim-1 sublevel pairs
    if (t == 0) {
        int np = 0;
        #pragma unroll 1
        for (int k = 0; k < NSQ; k++) {
            const unsigned long long nb = nbrs[k];
            const float fv = sval[k];
            const int v = vord[k];
            const int cnt = (int)(nb & 7ull);
            const bool outer = (nb & 8ull) != 0;

            int roots[4]; float maxs[4]; int nr = 0;
            #pragma unroll 1
            for (int i = 0; i < cnt; i++) {
                int a = (int)((nb >> (4 + 10 * i)) & 1023ull);
                int2 rec = node[a];
                while (rec.x != a) { a = rec.x; rec = node[a]; }
                bool dup = false;
                #pragma unroll
                for (int j = 0; j < 4; j++)
                    if (j < nr && roots[j] == a) dup = true;
                if (!dup) { roots[nr] = a; maxs[nr] = __int_as_float(rec.y); nr++; }
            }

            int rs;
            if (outer) {
                rs = OUTER;                 // outer (+inf) always survives
                #pragma unroll 1
                for (int j = 0; j < nr; j++) {
                    if (roots[j] == OUTER) continue;   // same component: no pair
                    if (maxs[j] > fv) { pw[np] = fv; pd[np] = maxs[j]; np++; }
                    node[roots[j]].x = OUTER;
                }
            } else if (nr > 0) {
                int best = 0;
                #pragma unroll
                for (int j = 1; j < 4; j++)
                    if (j < nr && maxs[j] > maxs[best]) best = j;
                rs = roots[best];
                #pragma unroll 1
                for (int j = 0; j < nr; j++) {
                    if (j == best) continue;
                    if (maxs[j] > fv) { pw[np] = fv; pd[np] = maxs[j]; np++; }
                    node[roots[j]].x = rs;
                }
            } else {
                rs = v;                     // isolated peak: own root (already init)
            }
            if (rs != v) node[v].x = rs;
            // compress touched neighbors straight to the final root
            #pragma unroll 1
            for (int i = 0; i < cnt; i++) {
                int id = (int)((nb >> (4 + 10 * i)) & 1023ull);
                node[id].x = rs;
            }
        }
        npairs = np;
    }
    __syncthreads();

    // ---- Phase 5: rank pairs by persistence desc (ties: later index first),
    //      emit top CARD as (birth, death); pad with Ip[0,0] ----
    const int np = npairs;
    if (t < np) {
        float pi = pd[t] - pw[t];
        int rank = 0;
        for (int j = 0; j < np; j++) {
            float pj = pd[j] - pw[j];
            rank += (pj > pi) || (pj == pi && j > t);
        }
        if (rank < CARD) {
            out[2 * rank]     = pw[t];
            out[2 * rank + 1] = pd[t];
        }
    }
    if (t < CARD && t >= np) {
        float pad = Ip[0];
        out[2 * t]     = pad;
        out[2 * t + 1] = pad;
    }
}

extern "C" void kernel_launch(void* const* d_in, const int* in_sizes, int n_in,
                              void* d_out, int out_size) {
    const float* I = (const float*)d_in[0];   // (28,28,2) float32
    const float* p = (const float*)d_in[1];   // (2,1) float32
    float* out = (float*)d_out;               // 100 float32
    (void)in_sizes; (void)n_in; (void)out_size;
    cubical_kernel<<<1, 1024>>>(I, p, out);
}

// round 6
// speedup vs baseline: 2.5281x; 2.5281x over previous
#include <cuda_runtime.h>

#define H 28
#define W 28
#define NSQ (H * W)          // 784 pixel nodes
#define OUTER NSQ            // node 784 = outer face, value +inf
#define NN (NSQ + 1)
#define NE_H (H * (W - 1))   // 756
#define NE_V ((H - 1) * W)   // 756
#define NE_B (2 * H + 2 * W) // 112
#define NE (NE_H + NE_V + NE_B) // 1624
#define NPAD 2048
#define CARD 50

__device__ __forceinline__ unsigned monof(float x) {
    unsigned u = __float_as_uint(x);
    return (u & 0x80000000u) ? ~u : (u | 0x80000000u);
}
__device__ __forceinline__ float invmonof(unsigned m) {
    return __uint_as_float((m & 0x80000000u) ? (m ^ 0x80000000u) : ~m);
}

__global__ __launch_bounds__(1024, 1)
void cubical_kernel(const float* __restrict__ I, const float* __restrict__ p,
                    float* __restrict__ out) {
    __shared__ float Ip[NSQ];
    __shared__ short g[NSQ];                 // steepest-ascent pointer -> peak
    __shared__ unsigned long long key[NPAD]; // (~monof(w))<<32 | pu<<10 | pv
    __shared__ int2  node[NN];               // .x parent, .y cmax bits
    __shared__ float pw[NSQ], pd[NSQ];       // pairs (birth, death)
    __shared__ int   npairs, npeaks;

    const int t = threadIdx.x;
    const float p0 = p[0], p1 = p[1];

    // ---- Phase 1: Ip = I . p, union-find init ----
    if (t < NSQ) {
        float v = fmaf(I[2 * t], p0, I[2 * t + 1] * p1);
        Ip[t] = v;
        node[t] = make_int2(t, __float_as_int(v));
    }
    if (t == 0) {
        node[OUTER] = make_int2(OUTER, __float_as_int(3.0e38f));
        npairs = 0; npeaks = 0;
    }
    __syncthreads();

    // ---- Phase 2: steepest ascent pointer (argmax neighbor, self if peak) ----
    if (t < NSQ) {
        const int row = t / W, col = t - row * W;
        const float fv = Ip[t];
        float best = fv; int bid = t;
        if (col > 0)     { float f = Ip[t - 1]; if (f > best) { best = f; bid = t - 1; } }
        if (col < W - 1) { float f = Ip[t + 1]; if (f > best) { best = f; bid = t + 1; } }
        if (row > 0)     { float f = Ip[t - W]; if (f > best) { best = f; bid = t - W; } }
        if (row < H - 1) { float f = Ip[t + W]; if (f > best) { best = f; bid = t + W; } }
        g[t] = (short)bid;
        if (bid == t) atomicAdd(&npeaks, 1);
    }
    __syncthreads();

    // ---- Phase 3: pointer doubling to peak (depth <= 783 -> 10 rounds) ----
    #pragma unroll
    for (int it = 0; it < 10; it++) {
        if (t < NSQ) g[t] = g[g[t]];
        __syncthreads();
    }

    // ---- Phase 4: build edge keys; internal (same-peak) edges -> sentinel ----
    for (int i = t; i < NPAD; i += blockDim.x) {
        unsigned long long kk = 0xFFFFFFFFFFFFFFFFull;
        if (i < NE) {
            int u, v; float w; int pu, pv;
            if (i < NE_H) {                       // horizontal
                int r = i / (W - 1), c = i % (W - 1);
                u = r * W + c; v = u + 1;
                w = fminf(Ip[u], Ip[v]);
                pu = g[u]; pv = g[v];
            } else if (i < NE_H + NE_V) {         // vertical
                int j = i - NE_H;
                u = j; v = j + W;
                w = fminf(Ip[u], Ip[v]);
                pu = g[u]; pv = g[v];
            } else {                              // boundary -> OUTER
                int j = i - NE_H - NE_V;
                int sq;
                if (j < W)              sq = j;
                else if (j < 2 * W)     sq = (H - 1) * W + (j - W);
                else if (j < 2 * W + H) sq = (j - 2 * W) * W;
                else                    sq = (j - 2 * W - H) * W + (W - 1);
                u = sq; v = OUTER; w = Ip[sq];
                pu = g[sq]; pv = OUTER;
            }
            if (pu != pv)
                kk = ((unsigned long long)(~monof(w)) << 32) |
                     ((unsigned long long)pu << 10) | (unsigned long long)pv;
        }
        key[i] = kk;
    }
    __syncthreads();

    // ---- Phase 5: bitonic sort ascending (== weight descending) ----
    for (int k2 = 2; k2 <= NPAD; k2 <<= 1) {
        for (int j = k2 >> 1; j >= 1; j >>= 1) {
            int l = ((t & ~(j - 1)) << 1) | (t & (j - 1));
            int m = l | j;
            unsigned long long kl = key[l], km = key[m];
            bool asc = ((l & k2) == 0);
            if ((kl > km) == asc) { key[l] = km; key[m] = kl; }
            __syncthreads();
        }
    }

    // ---- Phase 6: serial Kruskal on contracted graph (elder rule) ----
    if (t == 0) {
        const int target = npeaks;   // unions to fully connect peaks + outer
        int np = 0, unions = 0;
        #pragma unroll 1
        for (int k = 0; k < NPAD; k++) {
            const unsigned long long kk = key[k];
            unsigned wm = (unsigned)(kk >> 32);
            if (wm == 0xFFFFFFFFu) break;          // sentinel: done
            int a = (int)((kk >> 10) & 1023ull);
            int b = (int)(kk & 1023ull);
            const int u0 = a, v0 = b;
            int2 ra = node[a];
            int2 rb = node[b];
            while (ra.x != a) { a = ra.x; ra = node[a]; }
            while (rb.x != b) { b = rb.x; rb = node[b]; }
            if (a == b) {
                if (u0 != a) node[u0].x = a;
                if (v0 != a) node[v0].x = a;
                continue;
            }
            float w = invmonof(~wm);
            float Ma = __int_as_float(ra.y), Mb = __int_as_float(rb.y);
            float die = fminf(Ma, Mb);
            if (die > w) { pw[np] = w; pd[np] = die; np++; }
            int win, lose;
            if (Ma >= Mb) { win = a; lose = b; }
            else          { win = b; lose = a; }
            node[lose].x = win;
            if (u0 != win) node[u0].x = win;
            if (v0 != win) node[v0].x = win;
            if (++unions == target) break;
        }
        npairs = np;
    }
    __syncthreads();

    // ---- Phase 7: rank pairs by persistence desc, emit top CARD, pad ----
    const int np = npairs;
    if (t < np) {
        float pi = pd[t] - pw[t];
        int rank = 0;
        for (int j = 0; j < np; j++) {
            float pj = pd[j] - pw[j];
            rank += (pj > pi) || (pj == pi && j > t);
        }
        if (rank < CARD) {
            out[2 * rank]     = pw[t];
            out[2 * rank + 1] = pd[t];
        }
    }
    if (t < CARD && t >= np) {
        float pad = Ip[0];
        out[2 * t]     = pad;
        out[2 * t + 1] = pad;
    }
}

extern "C" void kernel_launch(void* const* d_in, const int* in_sizes, int n_in,
                              void* d_out, int out_size) {
    const float* I = (const float*)d_in[0];   // (28,28,2) float32
    const float* p = (const float*)d_in[1];   // (2,1) float32
    float* out = (float*)d_out;               // 100 float32
    (void)in_sizes; (void)n_in; (void)out_size;
    cubical_kernel<<<1, 1024>>>(I, p, out);
}

// round 7
// speedup vs baseline: 4.1392x; 1.6373x over previous
#include <cuda_runtime.h>

#define H 28
#define W 28
#define NSQ (H * W)          // 784 pixel nodes
#define OUTER NSQ            // node 784 = outer face, value +inf
#define NN (NSQ + 1)
#define NE_H (H * (W - 1))   // 756
#define NE_V ((H - 1) * W)   // 756
#define NE_B (2 * H + 2 * W) // 112
#define NE (NE_H + NE_V + NE_B) // 1624
#define KMAX 2048
#define HSZ 2048             // hash table slots
#define CARD 50
#define EMPTY64 0xFFFFFFFFFFFFFFFFull

__device__ __forceinline__ unsigned monof(float x) {
    unsigned u = __float_as_uint(x);
    return (u & 0x80000000u) ? ~u : (u | 0x80000000u);
}
__device__ __forceinline__ float invmonof(unsigned m) {
    return __uint_as_float((m & 0x80000000u) ? (m ^ 0x80000000u) : ~m);
}

__global__ __launch_bounds__(1024, 1)
void cubical_kernel(const float* __restrict__ I, const float* __restrict__ p,
                    float* __restrict__ out) {
    __shared__ float Ip[NSQ];
    __shared__ short g[NSQ];                   // steepest-ascent ptr -> peak
    __shared__ unsigned long long key[KMAX];   // (~monof(w))<<32 | pu<<10 | pv
    __shared__ unsigned long long scratch[HSZ]; // hash table, later pw/pd
    __shared__ int2  node[NN];                 // .x parent, .y cmax bits
    __shared__ int   npairs, npeaks, ecnt, smem_M;

    float* pw = (float*)scratch;               // pairs (birth) — after hash dead
    float* pd = ((float*)scratch) + NSQ;       // pairs (death)

    const int t = threadIdx.x;
    const int lane = t & 31;
    const int warp = t >> 5;
    const float p0 = p[0], p1 = p[1];

    // ---- Phase 1: Ip = I . p, union-find init, buffers init ----
    if (t < NSQ) {
        float v = fmaf(I[2 * t], p0, I[2 * t + 1] * p1);
        Ip[t] = v;
        node[t] = make_int2(t, __float_as_int(v));
    }
    if (t == 0) {
        node[OUTER] = make_int2(OUTER, __float_as_int(3.0e38f));
        npairs = 0; npeaks = 0; ecnt = 0;
    }
    for (int i = t; i < HSZ; i += 1024) scratch[i] = EMPTY64;
    for (int i = t; i < KMAX; i += 1024) key[i] = EMPTY64;
    __syncthreads();

    // ---- Phase 2: steepest-ascent pointer ----
    if (t < NSQ) {
        const int row = t / W, col = t - row * W;
        float best = Ip[t]; int bid = t;
        if (col > 0)     { float f = Ip[t - 1]; if (f > best) { best = f; bid = t - 1; } }
        if (col < W - 1) { float f = Ip[t + 1]; if (f > best) { best = f; bid = t + 1; } }
        if (row > 0)     { float f = Ip[t - W]; if (f > best) { best = f; bid = t - W; } }
        if (row < H - 1) { float f = Ip[t + W]; if (f > best) { best = f; bid = t + W; } }
        g[t] = (short)bid;
        if (bid == t) atomicAdd(&npeaks, 1);
    }
    __syncthreads();

    // ---- Phase 3: pointer doubling to peak ----
    #pragma unroll
    for (int it = 0; it < 10; it++) {
        if (t < NSQ) g[t] = g[g[t]];
        __syncthreads();
    }

    // ---- Phase 4: per-pair dedup via hash (keep max weight per peak pair) ----
    for (int i = t; i < NE; i += 1024) {
        int u, v; float w; int pu, pv;
        if (i < NE_H) {
            int r = i / (W - 1), c = i % (W - 1);
            u = r * W + c; v = u + 1;
            w = fminf(Ip[u], Ip[v]);
            pu = g[u]; pv = g[v];
        } else if (i < NE_H + NE_V) {
            int j = i - NE_H;
            u = j; v = j + W;
            w = fminf(Ip[u], Ip[v]);
            pu = g[u]; pv = g[v];
        } else {
            int j = i - NE_H - NE_V;
            int sq;
            if (j < W)              sq = j;
            else if (j < 2 * W)     sq = (H - 1) * W + (j - W);
            else if (j < 2 * W + H) sq = (j - 2 * W) * W;
            else                    sq = (j - 2 * W - H) * W + (W - 1);
            w = Ip[sq];
            pu = g[sq]; pv = OUTER;
        }
        if (pu != pv) {
            int pmin = pu < pv ? pu : pv;
            int pmax = pu < pv ? pv : pu;
            unsigned pair = ((unsigned)pmin << 10) | (unsigned)pmax;
            unsigned long long desired = ((unsigned long long)monof(w) << 20) | pair;
            unsigned s = (pair * 2654435761u) & (HSZ - 1);
            for (;;) {
                unsigned long long cur = scratch[s];
                if (cur == EMPTY64) {
                    unsigned long long old = atomicCAS(&scratch[s], EMPTY64, desired);
                    if (old == EMPTY64) break;
                    cur = old;
                }
                if ((unsigned)(cur & 0xFFFFFu) == pair) {
                    atomicMax(&scratch[s], desired);
                    break;
                }
                s = (s + 1) & (HSZ - 1);
            }
        }
    }
    __syncthreads();

    // ---- Phase 4.5: compact hash entries into key[] ----
    for (int i = t; i < HSZ; i += 1024) {
        unsigned long long e = scratch[i];
        if (e != EMPTY64) {
            int idx = atomicAdd(&ecnt, 1);
            unsigned wm = (unsigned)(e >> 20);
            key[idx] = ((unsigned long long)(~wm) << 32) | (e & 0xFFFFFull);
        }
    }
    __syncthreads();
    if (t == 0) {
        int n = ecnt;
        smem_M = (n <= 512) ? 512 : (n <= 1024 ? 1024 : 2048);
    }
    __syncthreads();
    const int M = smem_M;

    // ---- Phase 5: hybrid bitonic sort ascending over key[0..M) ----
    // warp w owns chunk [64w, 64w+64): regs v0=key[64w+lane], v1=key[64w+lane+32]
    {
        const bool act = (warp << 6) < M;
        const int i0 = (warp << 6) + lane;
        const int i1 = i0 + 32;
        unsigned long long v0 = 0, v1 = 0;
        const unsigned FULL = 0xffffffffu;

        if (act) { v0 = key[i0]; v1 = key[i1]; }
        // k2 = 2..64 entirely in registers
        if (act) {
            #pragma unroll
            for (int k2 = 2; k2 <= 64; k2 <<= 1) {
                if (k2 == 64) {
                    bool up = ((i0 & k2) == 0);
                    if ((v0 > v1) == up) { unsigned long long tm = v0; v0 = v1; v1 = tm; }
                }
                #pragma unroll
                for (int j = (k2 >= 32 ? 16 : (k2 >> 1)); j >= 1; j >>= 1) {
                    unsigned long long q0 = __shfl_xor_sync(FULL, v0, j);
                    unsigned long long q1 = __shfl_xor_sync(FULL, v1, j);
                    bool lower = (lane & j) == 0;
                    bool km0 = (lower == ((i0 & k2) == 0));
                    bool km1 = (lower == ((i1 & k2) == 0));
                    v0 = km0 ? (v0 < q0 ? v0 : q0) : (v0 > q0 ? v0 : q0);
                    v1 = km1 ? (v1 < q1 ? v1 : q1) : (v1 > q1 ? v1 : q1);
                }
            }
            key[i0] = v0; key[i1] = v1;
        }
        __syncthreads();

        for (int k2 = 128; k2 <= M; k2 <<= 1) {
            for (int j = k2 >> 1; j >= 64; j >>= 1) {
                if (t < (M >> 1)) {
                    int l = ((t & ~(j - 1)) << 1) | (t & (j - 1));
                    int m = l | j;
                    unsigned long long kl = key[l], km = key[m];
                    bool asc = ((l & k2) == 0);
                    if ((kl > km) == asc) { key[l] = km; key[m] = kl; }
                }
                __syncthreads();
            }
            if (act) {
                v0 = key[i0]; v1 = key[i1];
                {   // j = 32 (in-thread; i0&k2 == i1&k2 since k2 >= 128)
                    bool up = ((i0 & k2) == 0);
                    if ((v0 > v1) == up) { unsigned long long tm = v0; v0 = v1; v1 = tm; }
                }
                #pragma unroll
                for (int j = 16; j >= 1; j >>= 1) {
                    unsigned long long q0 = __shfl_xor_sync(FULL, v0, j);
                    unsigned long long q1 = __shfl_xor_sync(FULL, v1, j);
                    bool lower = (lane & j) == 0;
                    bool km0 = (lower == ((i0 & k2) == 0));
                    bool km1 = (lower == ((i1 & k2) == 0));
                    v0 = km0 ? (v0 < q0 ? v0 : q0) : (v0 > q0 ? v0 : q0);
                    v1 = km1 ? (v1 < q1 ? v1 : q1) : (v1 > q1 ? v1 : q1);
                }
                key[i0] = v0; key[i1] = v1;
            }
            __syncthreads();
        }
    }

    // ---- Phase 6: serial Kruskal on deduped contracted edges (elder rule) ----
    if (t == 0) {
        const int target = npeaks;
        int np = 0, unions = 0;
        #pragma unroll 1
        for (int k = 0; k < M; k++) {
            const unsigned long long kk = key[k];
            unsigned wm = (unsigned)(kk >> 32);
            if (wm == 0xFFFFFFFFu) break;         // sentinel
            int a = (int)((kk >> 10) & 1023ull);
            int b = (int)(kk & 1023ull);
            const int u0 = a, v0 = b;
            int2 ra = node[a];
            int2 rb = node[b];
            while (ra.x != a) { a = ra.x; ra = node[a]; }
            while (rb.x != b) { b = rb.x; rb = node[b]; }
            if (a == b) {
                if (u0 != a) node[u0].x = a;
                if (v0 != a) node[v0].x = a;
                continue;
            }
            float w = invmonof(~wm);
            float Ma = __int_as_float(ra.y), Mb = __int_as_float(rb.y);
            float die = fminf(Ma, Mb);
            if (die > w) { pw[np] = w; pd[np] = die; np++; }
            int win, lose;
            if (Ma >= Mb) { win = a; lose = b; }
            else          { win = b; lose = a; }
            node[lose].x = win;
            if (u0 != win) node[u0].x = win;
            if (v0 != win) node[v0].x = win;
            if (++unions == target) break;
        }
        npairs = np;
    }
    __syncthreads();

    // ---- Phase 7: rank pairs by persistence desc, emit top CARD, pad ----
    const int np = npairs;
    if (t < np) {
        float pi = pd[t] - pw[t];
        int rank = 0;
        for (int j = 0; j < np; j++) {
            float pj = pd[j] - pw[j];
            rank += (pj > pi) || (pj == pi && j > t);
        }
        if (rank < CARD) {
            out[2 * rank]     = pw[t];
            out[2 * rank + 1] = pd[t];
        }
    }
    if (t < CARD && t >= np) {
        float pad = Ip[0];
        out[2 * t]     = pad;
        out[2 * t + 1] = pad;
    }
}

extern "C" void kernel_launch(void* const* d_in, const int* in_sizes, int n_in,
                              void* d_out, int out_size) {
    const float* I = (const float*)d_in[0];   // (28,28,2) float32
    const float* p = (const float*)d_in[1];   // (2,1) float32
    float* out = (float*)d_out;               // 100 float32
    (void)in_sizes; (void)n_in; (void)out_size;
    cubical_kernel<<<1, 1024>>>(I, p, out);
}

// round 8
// speedup vs baseline: 6.0557x; 1.4630x over previous
#include <cuda_runtime.h>

#define H 28
#define W 28
#define NSQ (H * W)          // 784 pixels
#define NE_H (H * (W - 1))   // 756
#define NE_V ((H - 1) * W)   // 756
#define NE_B (2 * H + 2 * W) // 112
#define NE (NE_H + NE_V + NE_B) // 1624
#define KMAX 1024            // edge list / sort buffer
#define HSZ 1024             // hash slots
#define PMAX 512             // max dense nodes (peaks + outer)
#define CARD 50
#define EMPTY64 0xFFFFFFFFFFFFFFFFull

__device__ __forceinline__ unsigned monof(float x) {
    unsigned u = __float_as_uint(x);
    return (u & 0x80000000u) ? ~u : (u | 0x80000000u);
}
__device__ __forceinline__ float invmonof(unsigned m) {
    return __uint_as_float((m & 0x80000000u) ? (m ^ 0x80000000u) : ~m);
}

__global__ __launch_bounds__(1024, 1)
void cubical_kernel(const float* __restrict__ I, const float* __restrict__ p,
                    float* __restrict__ out) {
    __shared__ float Ip[NSQ];
    __shared__ short g[NSQ];                    // steepest-ascent ptr
    __shared__ short lbl[NSQ];                  // peak pixel -> dense id
    __shared__ unsigned long long key[KMAX];    // edges, then sort buffer
    __shared__ unsigned long long scratch[HSZ]; // hash -> mst list -> pw/pd
    __shared__ int   parent[PMAX];
    __shared__ float cmaxv[PMAX];               // dense id -> peak value
    __shared__ unsigned long long best[PMAX];   // Boruvka pick per root
    __shared__ int cnt_peaks, ecnt, nmst, npairs, roundun, smem_M;

    const int t = threadIdx.x;
    const int lane = t & 31;
    const int warp = t >> 5;
    const float p0 = p[0], p1 = p[1];

    // ---- Phase 1: Ip = I.p, buffer init ----
    if (t < NSQ) Ip[t] = fmaf(I[2 * t], p0, I[2 * t + 1] * p1);
    if (t == 0) { cnt_peaks = 0; ecnt = 0; nmst = 0; npairs = 0; }
    if (t < HSZ) scratch[t] = EMPTY64;
    if (t < PMAX) { parent[t] = t; best[t] = 0ull; }
    __syncthreads();

    // ---- Phase 2: steepest-ascent pointer ----
    if (t < NSQ) {
        const int row = t / W, col = t - row * W;
        float bestf = Ip[t]; int bid = t;
        if (col > 0)     { float f = Ip[t - 1]; if (f > bestf) { bestf = f; bid = t - 1; } }
        if (col < W - 1) { float f = Ip[t + 1]; if (f > bestf) { bestf = f; bid = t + 1; } }
        if (row > 0)     { float f = Ip[t - W]; if (f > bestf) { bestf = f; bid = t - W; } }
        if (row < H - 1) { float f = Ip[t + W]; if (f > bestf) { bestf = f; bid = t + W; } }
        g[t] = (short)bid;
    }
    __syncthreads();

    // ---- Phase 3: pointer doubling to peak ----
    #pragma unroll
    for (int it = 0; it < 10; it++) {
        if (t < NSQ) g[t] = g[g[t]];
        __syncthreads();
    }

    // ---- Phase 3.5: dense relabel of peaks; peak values ----
    if (t < NSQ && g[t] == t) {
        int id = atomicAdd(&cnt_peaks, 1);
        lbl[t] = (short)id;
        cmaxv[id] = Ip[t];
    }
    __syncthreads();
    const int P = cnt_peaks;        // outer id = P, NND = P+1
    const int NND = P + 1;
    if (t == 0) cmaxv[P] = 3.0e38f;
    __syncthreads();

    // ---- Phase 4: hash dedup (max weight per dense peak pair) ----
    for (int i = t; i < NE; i += 1024) {
        int pu, pv; float w;
        if (i < NE_H) {
            int r = i / (W - 1), c = i % (W - 1);
            int u = r * W + c, v = u + 1;
            w = fminf(Ip[u], Ip[v]);
            pu = lbl[g[u]]; pv = lbl[g[v]];
        } else if (i < NE_H + NE_V) {
            int j = i - NE_H;
            int u = j, v = j + W;
            w = fminf(Ip[u], Ip[v]);
            pu = lbl[g[u]]; pv = lbl[g[v]];
        } else {
            int j = i - NE_H - NE_V;
            int sq;
            if (j < W)              sq = j;
            else if (j < 2 * W)     sq = (H - 1) * W + (j - W);
            else if (j < 2 * W + H) sq = (j - 2 * W) * W;
            else                    sq = (j - 2 * W - H) * W + (W - 1);
            w = Ip[sq];
            pu = lbl[g[sq]]; pv = P;
        }
        if (pu != pv) {
            int pmin = pu < pv ? pu : pv;
            int pmax = pu < pv ? pv : pu;
            unsigned pair = ((unsigned)pmin << 10) | (unsigned)pmax;
            unsigned long long desired = ((unsigned long long)monof(w) << 20) | pair;
            unsigned s = (pair * 2654435761u) & (HSZ - 1);
            for (;;) {
                unsigned long long cur = scratch[s];
                if (cur == EMPTY64) {
                    unsigned long long old = atomicCAS(&scratch[s], EMPTY64, desired);
                    if (old == EMPTY64) break;
                    cur = old;
                }
                if ((unsigned)(cur & 0xFFFFFu) == pair) {
                    atomicMax(&scratch[s], desired);
                    break;
                }
                s = (s + 1) & (HSZ - 1);
            }
        }
    }
    __syncthreads();

    // ---- Phase 4.5: compact hash -> key[] (format wm<<20|pair) ----
    if (t < HSZ) {
        unsigned long long e = scratch[t];
        if (e != EMPTY64) {
            int idx = atomicAdd(&ecnt, 1);
            if (idx < KMAX) key[idx] = e;
        }
    }
    __syncthreads();
    const int EC = ecnt < KMAX ? ecnt : KMAX;

    // ---- Phase 5: Boruvka max-spanning-tree (MST edges == Kruskal unions) ----
    for (int round = 0; round < 10; round++) {
        if (t == 0) roundun = 0;
        __syncthreads();
        // each edge deposits itself on both endpoint roots (max by weight)
        if (t < EC) {
            unsigned long long e = key[t];
            unsigned pr = (unsigned)(e & 0xFFFFFull);
            int a = (int)(pr >> 10), b = (int)(pr & 1023u);
            int ra = parent[a], rb = parent[b];
            if (ra != rb) {
                atomicMax(&best[ra], e);
                atomicMax(&best[rb], e);
            }
        }
        __syncthreads();
        // union: each picking root hooks to the other root
        if (t < NND) {
            unsigned long long e = best[t];
            if (e != 0ull && parent[t] == t) {
                unsigned pr = (unsigned)(e & 0xFFFFFull);
                int a = (int)(pr >> 10), b = (int)(pr & 1023u);
                int ra = parent[a], rb = parent[b];
                parent[t] = (ra == t) ? rb : ra;
            }
        }
        __syncthreads();
        // break mutual 2-cycles (deterministic: smaller id becomes root)
        if (t < NND) {
            int pj = parent[t];
            if (pj != t && parent[pj] == t && t < pj) parent[t] = t;
        }
        __syncthreads();
        // committed picks append their MST edge (exactly once per union)
        if (t < NND) {
            unsigned long long e = best[t];
            if (e != 0ull && parent[t] != t) {
                int idx = atomicAdd(&nmst, 1);
                unsigned wm = (unsigned)(e >> 20);
                scratch[idx] = ((unsigned long long)(~wm) << 32) | (e & 0xFFFFFull);
                atomicAdd(&roundun, 1);
            }
            best[t] = 0ull;
        }
        __syncthreads();
        if (roundun == 0) break;
        // full pointer-jump compression (depth <= 512 -> 9 rounds)
        #pragma unroll
        for (int jr = 0; jr < 9; jr++) {
            if (t < NND) parent[t] = parent[parent[t]];
            __syncthreads();
        }
    }

    // ---- Phase 6: sort MST edges ascending (== weight descending) ----
    if (t == 0) {
        int M = 256;
        while (M < nmst) M <<= 1;
        smem_M = M;
    }
    __syncthreads();
    const int M = smem_M;
    const int nm = nmst;
    for (int i = t; i < M; i += 1024)
        key[i] = (i < nm) ? scratch[i] : EMPTY64;
    __syncthreads();
    {
        const bool act = (warp << 6) < M;
        const int i0 = (warp << 6) + lane;
        const int i1 = i0 + 32;
        unsigned long long v0 = 0, v1 = 0;
        const unsigned FULL = 0xffffffffu;
        if (act) {
            v0 = key[i0]; v1 = key[i1];
            #pragma unroll
            for (int k2 = 2; k2 <= 64; k2 <<= 1) {
                if (k2 == 64) {
                    bool up = ((i0 & k2) == 0);
                    if ((v0 > v1) == up) { unsigned long long tm = v0; v0 = v1; v1 = tm; }
                }
                #pragma unroll
                for (int j = (k2 >= 32 ? 16 : (k2 >> 1)); j >= 1; j >>= 1) {
                    unsigned long long q0 = __shfl_xor_sync(FULL, v0, j);
                    unsigned long long q1 = __shfl_xor_sync(FULL, v1, j);
                    bool lower = (lane & j) == 0;
                    bool km0 = (lower == ((i0 & k2) == 0));
                    bool km1 = (lower == ((i1 & k2) == 0));
                    v0 = km0 ? (v0 < q0 ? v0 : q0) : (v0 > q0 ? v0 : q0);
                    v1 = km1 ? (v1 < q1 ? v1 : q1) : (v1 > q1 ? v1 : q1);
                }
            }
            key[i0] = v0; key[i1] = v1;
        }
        __syncthreads();
        for (int k2 = 128; k2 <= M; k2 <<= 1) {
            for (int j = k2 >> 1; j >= 64; j >>= 1) {
                if (t < (M >> 1)) {
                    int l = ((t & ~(j - 1)) << 1) | (t & (j - 1));
                    int m = l | j;
                    unsigned long long kl = key[l], km = key[m];
                    bool asc = ((l & k2) == 0);
                    if ((kl > km) == asc) { key[l] = km; key[m] = kl; }
                }
                __syncthreads();
            }
            if (act) {
                v0 = key[i0]; v1 = key[i1];
                {
                    bool up = ((i0 & k2) == 0);
                    if ((v0 > v1) == up) { unsigned long long tm = v0; v0 = v1; v1 = tm; }
                }
                #pragma unroll
                for (int j = 16; j >= 1; j >>= 1) {
                    unsigned long long q0 = __shfl_xor_sync(FULL, v0, j);
                    unsigned long long q1 = __shfl_xor_sync(FULL, v1, j);
                    bool lower = (lane & j) == 0;
                    bool km0 = (lower == ((i0 & k2) == 0));
                    bool km1 = (lower == ((i1 & k2) == 0));
                    v0 = km0 ? (v0 < q0 ? v0 : q0) : (v0 > q0 ? v0 : q0);
                    v1 = km1 ? (v1 < q1 ? v1 : q1) : (v1 > q1 ? v1 : q1);
                }
                key[i0] = v0; key[i1] = v1;
            }
            __syncthreads();
        }
    }

    // ---- Phase 7: serial elder-rule scan over sorted MST edges ----
    float* pwv = (float*)scratch;          // mst list dead after copy
    float* pdv = ((float*)scratch) + PMAX;
    if (t < PMAX) parent[t] = t;           // reset UF (Boruvka consumed it)
    __syncthreads();
    if (t == 0) {
        int np = 0;
        #pragma unroll 1
        for (int k = 0; k < M; k++) {
            unsigned long long kk = key[k];
            unsigned wm = (unsigned)(kk >> 32);
            if (wm == 0xFFFFFFFFu) break;
            int a = (int)((kk >> 10) & 1023ull);
            int b = (int)(kk & 1023ull);
            int x = a, px = parent[x];
            while (px != x) { x = px; px = parent[x]; }
            int y = b, py = parent[y];
            while (py != y) { y = py; py = parent[y]; }
            if (x == y) continue;
            float w = invmonof(~wm);
            float Ma = cmaxv[x], Mb = cmaxv[y];
            float die = fminf(Ma, Mb);
            if (die > w) { pwv[np] = w; pdv[np] = die; np++; }
            int win, lose;
            if (Ma >= Mb) { win = x; lose = y; }
            else          { win = y; lose = x; }
            parent[lose] = win;
            parent[a] = win; parent[b] = win;
        }
        npairs = np;
    }
    __syncthreads();

    // ---- Phase 8: rank pairs by persistence desc, emit top CARD, pad ----
    const int np = npairs;
    if (t < np) {
        float pi = pdv[t] - pwv[t];
        int rank = 0;
        for (int j = 0; j < np; j++) {
            float pj = pdv[j] - pwv[j];
            rank += (pj > pi) || (pj == pi && j > t);
        }
        if (rank < CARD) {
            out[2 * rank]     = pwv[t];
            out[2 * rank + 1] = pdv[t];
        }
    }
    if (t < CARD && t >= np) {
        float pad = Ip[0];
        out[2 * t]     = pad;
        out[2 * t + 1] = pad;
    }
}

extern "C" void kernel_launch(void* const* d_in, const int* in_sizes, int n_in,
                              void* d_out, int out_size) {
    const float* I = (const float*)d_in[0];   // (28,28,2) float32
    const float* p = (const float*)d_in[1];   // (2,1) float32
    float* out = (float*)d_out;               // 100 float32
    (void)in_sizes; (void)n_in; (void)out_size;
    cubical_kernel<<<1, 1024>>>(I, p, out);
}